// round 4
// baseline (speedup 1.0000x reference)
#include <cuda_runtime.h>
#include <mma.h>
#include <cstdint>

using namespace nvcuda;

// ---------------- Problem constants ----------------
#define TOK  16384
#define DIM  1024
#define OUTD 4096

// ---------------- GEMM tiling ----------------
#define BM 256
#define BN 128
#define BK 32
#define NTHREADS 512
#define NCHUNK (DIM / BK)      // 32

// smem stage layout (floats, padded rows of 36)
#define ROWPAD 36
#define XS_BYTES (BM * ROWPAD * 4)          // 36864
#define WS_BYTES (BN * ROWPAD * 4)          // 18432
#define STAGE_BYTES (XS_BYTES + WS_BYTES)   // 55296
#define SMEM_TOTAL (2 * STAGE_BYTES)        // 110592

// ---------------- Device scratch ----------------
__device__ float g_Xr[TOK * DIM];           // tf32-rounded X (64 MiB)
__device__ float g_Wt[2][OUTD][DIM];        // tf32-rounded W^T (32 MiB)
__device__ int   g_perm[2 * TOK];           // routed token lists
__device__ int   g_cnt[2];

// ---------------- small helpers ----------------
__device__ __forceinline__ uint32_t smem_u32(const void* p) {
    uint32_t a;
    asm("{ .reg .u64 t; cvta.to.shared.u64 t, %1; cvt.u32.u64 %0, t; }" : "=r"(a) : "l"(p));
    return a;
}
__device__ __forceinline__ void cp16(uint32_t dst, const void* src) {
    asm volatile("cp.async.cg.shared.global [%0], [%1], 16;" :: "r"(dst), "l"(src));
}
#define CP_COMMIT() asm volatile("cp.async.commit_group;" ::: "memory")
#define CP_WAIT(n)  asm volatile("cp.async.wait_group %0;" :: "n"(n) : "memory")

// ---------------- Prep kernels ----------------
__global__ void zero_cnt() { if (threadIdx.x < 2) g_cnt[threadIdx.x] = 0; }

__global__ void compact_tokens(const int* __restrict__ tids) {
    int t = blockIdx.x * blockDim.x + threadIdx.x;   // 16384 threads
    int e = tids[t];
    int lane = threadIdx.x & 31;
    unsigned m1 = __ballot_sync(0xffffffffu, e == 1);
    unsigned me = (e == 1) ? m1 : ~m1;
    int leader = __ffs(me) - 1;
    int base = 0;
    if (lane == leader) base = atomicAdd(&g_cnt[e], __popc(me));
    base = __shfl_sync(0xffffffffu, base, leader);
    int pos = base + __popc(me & ((1u << lane) - 1u));
    g_perm[e * TOK + pos] = t;
}

__global__ void round_x(const float4* __restrict__ X) {
    int i = blockIdx.x * blockDim.x + threadIdx.x;
    float4 v = X[i];
    v.x = wmma::__float_to_tf32(v.x);
    v.y = wmma::__float_to_tf32(v.y);
    v.z = wmma::__float_to_tf32(v.z);
    v.w = wmma::__float_to_tf32(v.w);
    ((float4*)g_Xr)[i] = v;
}

__global__ void transpose_w(const float* __restrict__ W0, const float* __restrict__ W1) {
    __shared__ float t[32][33];
    const float* __restrict__ W = blockIdx.z ? W1 : W0;
    int n0 = blockIdx.x * 32, k0 = blockIdx.y * 32;
#pragma unroll
    for (int i = threadIdx.y; i < 32; i += 8)
        t[i][threadIdx.x] =
            wmma::__float_to_tf32(W[(size_t)(k0 + i) * OUTD + n0 + threadIdx.x]);
    __syncthreads();
    float* __restrict__ Wt = &g_Wt[blockIdx.z][0][0];
#pragma unroll
    for (int i = threadIdx.y; i < 32; i += 8)
        Wt[(size_t)(n0 + i) * DIM + k0 + threadIdx.x] = t[threadIdx.x][i];
}

// ---------------- Main routed GEMM: 16 warps, warp tile 64x32 ----------------
__global__ void __launch_bounds__(NTHREADS, 1)
mot_routed_gemm(const float* __restrict__ b0,
                const float* __restrict__ b1,
                float* __restrict__ out)
{
    const int e    = blockIdx.y >> 6;        // expert (grid.y = 128)
    const int tile = blockIdx.y & 63;        // row tile within expert
    const int col0 = blockIdx.x * BN;
    const int cnt  = g_cnt[e];
    const int row0 = tile * BM;
    if (row0 >= cnt) return;

    extern __shared__ char dynsm[];
    __shared__ int   tokS[BM];
    __shared__ float biasS[BN];

    const int tid  = threadIdx.x;
    const int warp = tid >> 5;
    const int warp_m = warp >> 2;            // 0..3 -> rows warp_m*64
    const int warp_n = warp & 3;             // 0..3 -> cols warp_n*32

    // token list + bias
    {
        if (tid < BM) {
            int r = row0 + tid;
            tokS[tid] = (r < cnt) ? g_perm[e * TOK + r] : 0;
        }
        if (tid < BN) biasS[tid] = (e ? b1 : b0)[col0 + tid];
    }
    __syncthreads();

    // per-thread fixed load coordinates
    const int lr = tid >> 3;                 // 0..63
    const int lc = tid & 7;                  // 16B chunk within 128B row
    int myTok[4];
#pragma unroll
    for (int j = 0; j < 4; j++) myTok[j] = tokS[lr + 64 * j];

    const uint32_t sm = smem_u32(dynsm);
    const float* __restrict__ Wtp = &g_Wt[e][col0][0];

    auto load_stage = [&](int s, int kk) {
        const uint32_t xs = sm + s * STAGE_BYTES;
        const uint32_t ws = xs + XS_BYTES;
#pragma unroll
        for (int j = 0; j < 4; j++) {        // X: 256 rows
            int row = lr + 64 * j;
            cp16(xs + (uint32_t)(row * (ROWPAD * 4) + lc * 16),
                 g_Xr + (size_t)myTok[j] * DIM + kk + lc * 4);
        }
#pragma unroll
        for (int j = 0; j < 2; j++) {        // W: 128 rows
            int n = lr + 64 * j;
            cp16(ws + (uint32_t)(n * (ROWPAD * 4) + lc * 16),
                 Wtp + (size_t)n * DIM + kk + lc * 4);
        }
    };

    // accumulators: 64x32 warp tile = 4x2 of 16x16
    wmma::fragment<wmma::accumulator, 16, 16, 8, float> acc[4][2];
#pragma unroll
    for (int i = 0; i < 4; i++)
#pragma unroll
        for (int j = 0; j < 2; j++) wmma::fill_fragment(acc[i][j], 0.0f);

    // pipeline
    load_stage(0, 0);
    CP_COMMIT();

    for (int c = 0; c < NCHUNK; c++) {
        if (c + 1 < NCHUNK) {
            load_stage((c + 1) & 1, (c + 1) * BK);
            CP_COMMIT();
            CP_WAIT(1);
        } else {
            CP_WAIT(0);
        }
        __syncthreads();

        const float* xb = (const float*)(dynsm + (c & 1) * STAGE_BYTES);
        const float* wb = xb + BM * ROWPAD;
#pragma unroll
        for (int ks = 0; ks < 4; ks++) {
            wmma::fragment<wmma::matrix_a, 16, 16, 8, wmma::precision::tf32,
                           wmma::row_major> af[4];
            wmma::fragment<wmma::matrix_b, 16, 16, 8, wmma::precision::tf32,
                           wmma::col_major> bf[2];
#pragma unroll
            for (int i = 0; i < 4; i++)
                wmma::load_matrix_sync(af[i],
                    xb + (warp_m * 64 + i * 16) * ROWPAD + ks * 8, ROWPAD);
#pragma unroll
            for (int j = 0; j < 2; j++)
                wmma::load_matrix_sync(bf[j],
                    wb + (warp_n * 32 + j * 16) * ROWPAD + ks * 8, ROWPAD);
#pragma unroll
            for (int i = 0; i < 4; i++)
#pragma unroll
                for (int j = 0; j < 2; j++)
                    wmma::mma_sync(acc[i][j], af[i], bf[j], acc[i][j]);
        }
        __syncthreads();
    }

    // ---- Epilogue: two 128x128 halves staged through smem ----
    float* Cs = (float*)dynsm;               // 128*128 floats = 64 KB
    float* __restrict__ oute = out + (size_t)e * TOK * OUTD;
    float* __restrict__ outo = out + (size_t)(1 - e) * TOK * OUTD;

#pragma unroll
    for (int h = 0; h < 2; h++) {
        if ((warp_m >> 1) == h) {
            int lm = (warp_m & 1) * 64;
#pragma unroll
            for (int i = 0; i < 4; i++)
#pragma unroll
                for (int j = 0; j < 2; j++)
                    wmma::store_matrix_sync(
                        Cs + (lm + i * 16) * BN + warp_n * 32 + j * 16,
                        acc[i][j], BN, wmma::mem_row_major);
        }
        __syncthreads();

#pragma unroll
        for (int q = 0; q < 8; q++) {
            int idx = tid + q * NTHREADS;    // float4 index, 0..4095
            int r  = idx >> 5;               // 0..127
            int c4 = idx & 31;
            int grow = h * 128 + r;
            if (row0 + grow < cnt) {
                int token = tokS[grow];
                float4 v = ((const float4*)Cs)[idx];
                float4 bb = *(const float4*)&biasS[c4 * 4];
                v.x += bb.x; v.y += bb.y; v.z += bb.z; v.w += bb.w;
                *(float4*)(oute + ((size_t)token * OUTD) + col0 + c4 * 4) = v;
                float4 z = make_float4(0.f, 0.f, 0.f, 0.f);
                *(float4*)(outo + ((size_t)token * OUTD) + col0 + c4 * 4) = z;
            }
        }
        __syncthreads();
    }
}

// ---------------- Launch ----------------
extern "C" void kernel_launch(void* const* d_in, const int* in_sizes, int n_in,
                              void* d_out, int out_size)
{
    const float* X   = (const float*)d_in[0];
    const int*   tid = (const int*)  d_in[1];
    const float* W0  = (const float*)d_in[2];
    const float* b0  = (const float*)d_in[3];
    const float* W1  = (const float*)d_in[4];
    const float* b1  = (const float*)d_in[5];
    float* out = (float*)d_out;

    cudaFuncSetAttribute(mot_routed_gemm,
                         cudaFuncAttributeMaxDynamicSharedMemorySize, SMEM_TOTAL);

    zero_cnt<<<1, 32>>>();
    compact_tokens<<<TOK / 256, 256>>>(tid);
    round_x<<<(TOK * DIM / 4) / 256, 256>>>((const float4*)X);
    transpose_w<<<dim3(OUTD / 32, DIM / 32, 2), dim3(32, 8)>>>(W0, W1);

    dim3 grid(OUTD / BN, 128);               // 32 x (2 experts * 64 row tiles)
    mot_routed_gemm<<<grid, NTHREADS, SMEM_TOTAL>>>(b0, b1, out);
}

// round 5
// speedup vs baseline: 1.9894x; 1.9894x over previous
#include <cuda_runtime.h>
#include <mma.h>
#include <cstdint>

using namespace nvcuda;

// ---------------- Problem constants ----------------
#define TOK  16384
#define DIM  1024
#define OUTD 4096

// ---------------- GEMM tiling ----------------
#define BM 256
#define BN 128
#define BK 32
#define NTHREADS 256
#define NCHUNK (DIM / BK)      // 32

// smem stage layout (floats, padded rows of 36)
#define ROWPAD 36
#define XS_BYTES (BM * ROWPAD * 4)          // 36864
#define WS_BYTES (BN * ROWPAD * 4)          // 18432
#define STAGE_BYTES (XS_BYTES + WS_BYTES)   // 55296
#define SMEM_TOTAL (2 * STAGE_BYTES)        // 110592

// ---------------- Device scratch ----------------
__device__ float g_Xr[TOK * DIM];           // tf32-rounded X (64 MiB)
__device__ float g_Wt[2][OUTD][DIM];        // tf32-rounded W^T (32 MiB)
__device__ int   g_perm[2 * TOK];           // routed token lists
__device__ int   g_cnt[2];

// ---------------- small helpers ----------------
__device__ __forceinline__ uint32_t smem_u32(const void* p) {
    uint32_t a;
    asm("{ .reg .u64 t; cvta.to.shared.u64 t, %1; cvt.u32.u64 %0, t; }" : "=r"(a) : "l"(p));
    return a;
}
__device__ __forceinline__ void cp16(uint32_t dst, const void* src) {
    asm volatile("cp.async.cg.shared.global [%0], [%1], 16;" :: "r"(dst), "l"(src));
}
#define CP_COMMIT() asm volatile("cp.async.commit_group;" ::: "memory")
#define CP_WAIT(n)  asm volatile("cp.async.wait_group %0;" :: "n"(n) : "memory")

__device__ __forceinline__ void mma16n8k8(float* d, const uint32_t* a, const uint32_t* b) {
    asm volatile(
        "mma.sync.aligned.m16n8k8.row.col.f32.tf32.tf32.f32 "
        "{%0,%1,%2,%3}, {%4,%5,%6,%7}, {%8,%9}, {%0,%1,%2,%3};"
        : "+f"(d[0]), "+f"(d[1]), "+f"(d[2]), "+f"(d[3])
        : "r"(a[0]), "r"(a[1]), "r"(a[2]), "r"(a[3]), "r"(b[0]), "r"(b[1]));
}

// ---------------- Prep kernels ----------------
__global__ void zero_cnt() { if (threadIdx.x < 2) g_cnt[threadIdx.x] = 0; }

__global__ void compact_tokens(const int* __restrict__ tids) {
    int t = blockIdx.x * blockDim.x + threadIdx.x;
    int e = tids[t];
    int lane = threadIdx.x & 31;
    unsigned m1 = __ballot_sync(0xffffffffu, e == 1);
    unsigned me = (e == 1) ? m1 : ~m1;
    int leader = __ffs(me) - 1;
    int base = 0;
    if (lane == leader) base = atomicAdd(&g_cnt[e], __popc(me));
    base = __shfl_sync(0xffffffffu, base, leader);
    int pos = base + __popc(me & ((1u << lane) - 1u));
    g_perm[e * TOK + pos] = t;
}

__global__ void round_x(const float4* __restrict__ X) {
    int i = blockIdx.x * blockDim.x + threadIdx.x;
    float4 v = X[i];
    v.x = wmma::__float_to_tf32(v.x);
    v.y = wmma::__float_to_tf32(v.y);
    v.z = wmma::__float_to_tf32(v.z);
    v.w = wmma::__float_to_tf32(v.w);
    ((float4*)g_Xr)[i] = v;
}

__global__ void transpose_w(const float* __restrict__ W0, const float* __restrict__ W1) {
    __shared__ float t[32][33];
    const float* __restrict__ W = blockIdx.z ? W1 : W0;
    int n0 = blockIdx.x * 32, k0 = blockIdx.y * 32;
#pragma unroll
    for (int i = threadIdx.y; i < 32; i += 8)
        t[i][threadIdx.x] =
            wmma::__float_to_tf32(W[(size_t)(k0 + i) * OUTD + n0 + threadIdx.x]);
    __syncthreads();
    float* __restrict__ Wt = &g_Wt[blockIdx.z][0][0];
#pragma unroll
    for (int i = threadIdx.y; i < 32; i += 8)
        Wt[(size_t)(n0 + i) * DIM + k0 + threadIdx.x] = t[threadIdx.x][i];
}

// ---------------- Main routed GEMM: 8 warps, warp tile 64x64, raw mma ----------------
__global__ void __launch_bounds__(NTHREADS, 1)
mot_routed_gemm(const float* __restrict__ b0,
                const float* __restrict__ b1,
                float* __restrict__ out)
{
    const int e    = blockIdx.y >> 6;        // expert
    const int tile = blockIdx.y & 63;        // row tile within expert
    const int col0 = blockIdx.x * BN;
    const int cnt  = g_cnt[e];
    const int row0 = tile * BM;
    if (row0 >= cnt) return;

    extern __shared__ char dynsm[];
    __shared__ int   tokS[BM];
    __shared__ float biasS[BN];

    const int tid  = threadIdx.x;
    const int warp = tid >> 5;
    const int lane = tid & 31;
    const int grp  = lane >> 2;              // 0..7
    const int tig  = lane & 3;               // 0..3
    const int warp_m = warp >> 1;            // 0..3 -> rows warp_m*64
    const int warp_n = warp & 1;             // 0..1 -> cols warp_n*64

    // token list + bias
    {
        int r = row0 + tid;
        tokS[tid] = (r < cnt) ? g_perm[e * TOK + r] : 0;
        if (tid < BN) biasS[tid] = (e ? b1 : b0)[col0 + tid];
    }
    __syncthreads();

    // per-thread fixed load coordinates
    const int lr = tid >> 3;                 // 0..31
    const int lc = tid & 7;                  // 16B chunk within 128B row
    int myTok[8];
#pragma unroll
    for (int j = 0; j < 8; j++) myTok[j] = tokS[lr + 32 * j];

    const uint32_t sm = smem_u32(dynsm);
    const float* __restrict__ Wtp = &g_Wt[e][col0][0];

    auto load_stage = [&](int s, int kk) {
        const uint32_t xs = sm + s * STAGE_BYTES;
        const uint32_t ws = xs + XS_BYTES;
#pragma unroll
        for (int j = 0; j < 8; j++) {
            int row = lr + 32 * j;
            cp16(xs + (uint32_t)(row * (ROWPAD * 4) + lc * 16),
                 g_Xr + (size_t)myTok[j] * DIM + kk + lc * 4);
        }
#pragma unroll
        for (int j = 0; j < 4; j++) {
            int n = lr + 32 * j;
            cp16(ws + (uint32_t)(n * (ROWPAD * 4) + lc * 16),
                 Wtp + (size_t)n * DIM + kk + lc * 4);
        }
    };

    // accumulators: warp tile 64x64 = 4 mtiles (m16) x 8 ntiles (n8)
    float acc[4][8][4];
#pragma unroll
    for (int i = 0; i < 4; i++)
#pragma unroll
        for (int j = 0; j < 8; j++)
#pragma unroll
            for (int q = 0; q < 4; q++) acc[i][j][q] = 0.0f;

    // pipeline
    load_stage(0, 0);
    CP_COMMIT();

    for (int c = 0; c < NCHUNK; c++) {
        if (c + 1 < NCHUNK) {
            load_stage((c + 1) & 1, (c + 1) * BK);
            CP_COMMIT();
            CP_WAIT(1);
        } else {
            CP_WAIT(0);
        }
        __syncthreads();

        const float* xb = (const float*)(dynsm + (c & 1) * STAGE_BYTES);
        const float* wb = xb + BM * ROWPAD;

        // base offsets for this thread's fragment elements
        const float* xA = xb + (warp_m * 64 + grp) * ROWPAD + tig;
        const float* wB = wb + (warp_n * 64 + grp) * ROWPAD + tig;

#pragma unroll
        for (int ks = 0; ks < 4; ks++) {
            const int ko = ks * 8;
            uint32_t a[4][4];
#pragma unroll
            for (int i = 0; i < 4; i++) {
                const float* p = xA + i * 16 * ROWPAD + ko;
                a[i][0] = __float_as_uint(p[0]);
                a[i][1] = __float_as_uint(p[8 * ROWPAD]);
                a[i][2] = __float_as_uint(p[4]);
                a[i][3] = __float_as_uint(p[8 * ROWPAD + 4]);
            }
            uint32_t b[8][2];
#pragma unroll
            for (int j = 0; j < 8; j++) {
                const float* p = wB + j * 8 * ROWPAD + ko;
                b[j][0] = __float_as_uint(p[0]);
                b[j][1] = __float_as_uint(p[4]);
            }
#pragma unroll
            for (int i = 0; i < 4; i++)
#pragma unroll
                for (int j = 0; j < 8; j++)
                    mma16n8k8(acc[i][j], a[i], b[j]);
        }
        __syncthreads();
    }

    // ---- Epilogue: direct register -> gmem (value plane + zero plane) ----
    float* __restrict__ oute = out + (size_t)e * TOK * OUTD;
    float* __restrict__ outo = out + (size_t)(1 - e) * TOK * OUTD;
    const int colbase = col0 + warp_n * 64 + 2 * tig;

    float2 biasv[8];
#pragma unroll
    for (int j = 0; j < 8; j++)
        biasv[j] = *(const float2*)&biasS[warp_n * 64 + j * 8 + 2 * tig];

#pragma unroll
    for (int i = 0; i < 4; i++) {
        const int lr0 = warp_m * 64 + i * 16 + grp;
        const int lr1 = lr0 + 8;
        const bool v0 = (row0 + lr0) < cnt;
        const bool v1 = (row0 + lr1) < cnt;
        const int t0 = tokS[lr0];
        const int t1 = tokS[lr1];
        float* p0e = oute + (size_t)t0 * OUTD + colbase;
        float* p0o = outo + (size_t)t0 * OUTD + colbase;
        float* p1e = oute + (size_t)t1 * OUTD + colbase;
        float* p1o = outo + (size_t)t1 * OUTD + colbase;
        const float2 z = make_float2(0.f, 0.f);
#pragma unroll
        for (int j = 0; j < 8; j++) {
            if (v0) {
                float2 v = make_float2(acc[i][j][0] + biasv[j].x,
                                       acc[i][j][1] + biasv[j].y);
                *(float2*)(p0e + j * 8) = v;
                *(float2*)(p0o + j * 8) = z;
            }
            if (v1) {
                float2 v = make_float2(acc[i][j][2] + biasv[j].x,
                                       acc[i][j][3] + biasv[j].y);
                *(float2*)(p1e + j * 8) = v;
                *(float2*)(p1o + j * 8) = z;
            }
        }
    }
}

// ---------------- Launch ----------------
extern "C" void kernel_launch(void* const* d_in, const int* in_sizes, int n_in,
                              void* d_out, int out_size)
{
    const float* X   = (const float*)d_in[0];
    const int*   tid = (const int*)  d_in[1];
    const float* W0  = (const float*)d_in[2];
    const float* b0  = (const float*)d_in[3];
    const float* W1  = (const float*)d_in[4];
    const float* b1  = (const float*)d_in[5];
    float* out = (float*)d_out;

    cudaFuncSetAttribute(mot_routed_gemm,
                         cudaFuncAttributeMaxDynamicSharedMemorySize, SMEM_TOTAL);

    zero_cnt<<<1, 32>>>();
    compact_tokens<<<TOK / 256, 256>>>(tid);
    round_x<<<(TOK * DIM / 4) / 256, 256>>>((const float4*)X);
    transpose_w<<<dim3(OUTD / 32, DIM / 32, 2), dim3(32, 8)>>>(W0, W1);

    dim3 grid(OUTD / BN, 128);               // 32 x (2 experts * 64 row tiles)
    mot_routed_gemm<<<grid, NTHREADS, SMEM_TOTAL>>>(b0, b1, out);
}

// round 7
// speedup vs baseline: 2.8859x; 1.4507x over previous
#include <cuda_runtime.h>
#include <cuda_fp16.h>
#include <cstdint>

// ---------------- Problem constants ----------------
#define TOK  16384
#define DIM  1024
#define OUTD 4096

// ---------------- GEMM tiling ----------------
#define BM 256
#define BN 128
#define BK 32                   // K halves per chunk
#define NTHREADS 256
#define NCHUNK (DIM / BK)       // 32

// smem stage layout (halves, padded rows of 40 halves = 80 bytes)
#define PH 40
#define XS_BYTES (BM * PH * 2)              // 20480
#define WS_BYTES (BN * PH * 2)              // 10240
#define STAGE_BYTES (XS_BYTES + WS_BYTES)   // 30720
#define SMEM_TOTAL (2 * STAGE_BYTES)        // 61440

// ---------------- Device scratch ----------------
__device__ __half g_Xh[TOK * DIM];          // fp16 X (32 MiB)
__device__ __half g_Wth[2][OUTD][DIM];      // fp16 W^T (16 MiB)
__device__ int    g_perm[2 * TOK];          // routed token lists
__device__ int    g_cnt[2];

// ---------------- small helpers ----------------
__device__ __forceinline__ uint32_t smem_u32(const void* p) {
    uint32_t a;
    asm("{ .reg .u64 t; cvta.to.shared.u64 t, %1; cvt.u32.u64 %0, t; }" : "=r"(a) : "l"(p));
    return a;
}
__device__ __forceinline__ void cp16(uint32_t dst, const void* src) {
    asm volatile("cp.async.cg.shared.global [%0], [%1], 16;" :: "r"(dst), "l"(src));
}
#define CP_COMMIT() asm volatile("cp.async.commit_group;" ::: "memory")
#define CP_WAIT(n)  asm volatile("cp.async.wait_group %0;" :: "n"(n) : "memory")

__device__ __forceinline__ void mma16n8k16(float* d, const uint32_t* a, const uint32_t* b) {
    asm volatile(
        "mma.sync.aligned.m16n8k16.row.col.f32.f16.f16.f32 "
        "{%0,%1,%2,%3}, {%4,%5,%6,%7}, {%8,%9}, {%0,%1,%2,%3};"
        : "+f"(d[0]), "+f"(d[1]), "+f"(d[2]), "+f"(d[3])
        : "r"(a[0]), "r"(a[1]), "r"(a[2]), "r"(a[3]), "r"(b[0]), "r"(b[1]));
}

// ---------------- Prep kernels ----------------
__global__ void zero_cnt() { if (threadIdx.x < 2) g_cnt[threadIdx.x] = 0; }

__global__ void compact_tokens(const int* __restrict__ tids) {
    int t = blockIdx.x * blockDim.x + threadIdx.x;
    int e = tids[t];
    int lane = threadIdx.x & 31;
    unsigned m1 = __ballot_sync(0xffffffffu, e == 1);
    unsigned me = (e == 1) ? m1 : ~m1;
    int leader = __ffs(me) - 1;
    int base = 0;
    if (lane == leader) base = atomicAdd(&g_cnt[e], __popc(me));
    base = __shfl_sync(0xffffffffu, base, leader);
    int pos = base + __popc(me & ((1u << lane) - 1u));
    g_perm[e * TOK + pos] = t;
}

__global__ void halve_x(const float4* __restrict__ X) {
    int i = blockIdx.x * blockDim.x + threadIdx.x;   // TOK*DIM/4 threads
    float4 v = X[i];
    __half2 h0 = __floats2half2_rn(v.x, v.y);
    __half2 h1 = __floats2half2_rn(v.z, v.w);
    uint2 pk;
    pk.x = *(uint32_t*)&h0;
    pk.y = *(uint32_t*)&h1;
    ((uint2*)g_Xh)[i] = pk;
}

__global__ void transpose_w(const float* __restrict__ W0, const float* __restrict__ W1) {
    __shared__ float t[32][33];
    const float* __restrict__ W = blockIdx.z ? W1 : W0;
    int n0 = blockIdx.x * 32, k0 = blockIdx.y * 32;
#pragma unroll
    for (int i = threadIdx.y; i < 32; i += 8)
        t[i][threadIdx.x] = W[(size_t)(k0 + i) * OUTD + n0 + threadIdx.x];
    __syncthreads();
    __half* __restrict__ Wt = &g_Wth[blockIdx.z][0][0];
#pragma unroll
    for (int i = threadIdx.y; i < 32; i += 8)
        Wt[(size_t)(n0 + i) * DIM + k0 + threadIdx.x] = __float2half_rn(t[threadIdx.x][i]);
}

// ---------------- Main routed GEMM: 8 warps, warp tile 64x64, fp16 mma ----------------
__global__ void __launch_bounds__(NTHREADS, 1)
mot_routed_gemm(const float* __restrict__ b0,
                const float* __restrict__ b1,
                float* __restrict__ out)
{
    const int e    = blockIdx.y >> 6;        // expert
    const int tile = blockIdx.y & 63;        // row tile within expert
    const int col0 = blockIdx.x * BN;
    const int cnt  = g_cnt[e];
    const int row0 = tile * BM;
    if (row0 >= cnt) return;

    extern __shared__ char dynsm[];
    __shared__ int   tokS[BM];
    __shared__ float biasS[BN];

    const int tid  = threadIdx.x;
    const int warp = tid >> 5;
    const int lane = tid & 31;
    const int grp  = lane >> 2;              // 0..7
    const int tig  = lane & 3;               // 0..3
    const int warp_m = warp >> 1;            // 0..3 -> rows warp_m*64
    const int warp_n = warp & 1;             // 0..1 -> cols warp_n*64

    // token list + bias
    {
        if (tid < BM) {
            int r = row0 + tid;
            tokS[tid] = (r < cnt) ? g_perm[e * TOK + r] : 0;
        }
        if (tid < BN) biasS[tid] = (e ? b1 : b0)[col0 + tid];
    }
    __syncthreads();

    // per-thread fixed load coordinates: 16B chunk = 8 halves
    const int lr = tid >> 2;                 // 0..63
    const int lc = tid & 3;                  // chunk within 64B row
    int myTok[4];
#pragma unroll
    for (int j = 0; j < 4; j++) myTok[j] = tokS[lr + 64 * j];

    const uint32_t sm = smem_u32(dynsm);
    const __half* __restrict__ Wtp = &g_Wth[e][col0][0];

    auto load_stage = [&](int s, int kk) {
        const uint32_t xs = sm + s * STAGE_BYTES;
        const uint32_t ws = xs + XS_BYTES;
#pragma unroll
        for (int j = 0; j < 4; j++) {        // X: 256 rows x 32 halves
            int row = lr + 64 * j;
            cp16(xs + (uint32_t)(row * (PH * 2) + lc * 16),
                 g_Xh + (size_t)myTok[j] * DIM + kk + lc * 8);
        }
#pragma unroll
        for (int j = 0; j < 2; j++) {        // W: 128 rows x 32 halves
            int n = lr + 64 * j;
            cp16(ws + (uint32_t)(n * (PH * 2) + lc * 16),
                 Wtp + (size_t)n * DIM + kk + lc * 8);
        }
    };

    // accumulators: warp tile 64x64 = 4 mtiles (m16) x 8 ntiles (n8)
    float acc[4][8][4];
#pragma unroll
    for (int i = 0; i < 4; i++)
#pragma unroll
        for (int j = 0; j < 8; j++)
#pragma unroll
            for (int q = 0; q < 4; q++) acc[i][j][q] = 0.0f;

    // pipeline
    load_stage(0, 0);
    CP_COMMIT();

    for (int c = 0; c < NCHUNK; c++) {
        if (c + 1 < NCHUNK) {
            load_stage((c + 1) & 1, (c + 1) * BK);
            CP_COMMIT();
            CP_WAIT(1);
        } else {
            CP_WAIT(0);
        }
        __syncthreads();

        const __half* xb = (const __half*)(dynsm + (c & 1) * STAGE_BYTES);
        const __half* wb = xb + BM * PH;

        // base pointers for this thread's fragment elements
        const __half* xA = xb + (warp_m * 64 + grp) * PH + 2 * tig;
        const __half* wB = wb + (warp_n * 64 + grp) * PH + 2 * tig;

#pragma unroll
        for (int ks = 0; ks < 2; ks++) {
            const int ko = ks * 16;
            uint32_t a[4][4];
#pragma unroll
            for (int i = 0; i < 4; i++) {
                const __half* p = xA + i * 16 * PH + ko;
                a[i][0] = *(const uint32_t*)(p);
                a[i][1] = *(const uint32_t*)(p + 8 * PH);
                a[i][2] = *(const uint32_t*)(p + 8);
                a[i][3] = *(const uint32_t*)(p + 8 * PH + 8);
            }
            uint32_t b[8][2];
#pragma unroll
            for (int j = 0; j < 8; j++) {
                const __half* p = wB + j * 8 * PH + ko;
                b[j][0] = *(const uint32_t*)(p);
                b[j][1] = *(const uint32_t*)(p + 8);
            }
#pragma unroll
            for (int i = 0; i < 4; i++)
#pragma unroll
                for (int j = 0; j < 8; j++)
                    mma16n8k16(acc[i][j], a[i], b[j]);
        }
        __syncthreads();
    }

    // ---- Epilogue: direct register -> gmem (value plane + zero plane) ----
    float* __restrict__ oute = out + (size_t)e * TOK * OUTD;
    float* __restrict__ outo = out + (size_t)(1 - e) * TOK * OUTD;
    const int colbase = col0 + warp_n * 64 + 2 * tig;

    float2 biasv[8];
#pragma unroll
    for (int j = 0; j < 8; j++)
        biasv[j] = *(const float2*)&biasS[warp_n * 64 + j * 8 + 2 * tig];

#pragma unroll
    for (int i = 0; i < 4; i++) {
        const int lr0 = warp_m * 64 + i * 16 + grp;
        const int lr1 = lr0 + 8;
        const bool v0 = (row0 + lr0) < cnt;
        const bool v1 = (row0 + lr1) < cnt;
        const int t0 = tokS[lr0];
        const int t1 = tokS[lr1];
        float* p0e = oute + (size_t)t0 * OUTD + colbase;
        float* p0o = outo + (size_t)t0 * OUTD + colbase;
        float* p1e = oute + (size_t)t1 * OUTD + colbase;
        float* p1o = outo + (size_t)t1 * OUTD + colbase;
        const float2 z = make_float2(0.f, 0.f);
#pragma unroll
        for (int j = 0; j < 8; j++) {
            if (v0) {
                float2 v = make_float2(acc[i][j][0] + biasv[j].x,
                                       acc[i][j][1] + biasv[j].y);
                *(float2*)(p0e + j * 8) = v;
                *(float2*)(p0o + j * 8) = z;
            }
            if (v1) {
                float2 v = make_float2(acc[i][j][2] + biasv[j].x,
                                       acc[i][j][3] + biasv[j].y);
                *(float2*)(p1e + j * 8) = v;
                *(float2*)(p1o + j * 8) = z;
            }
        }
    }
}

// ---------------- Launch ----------------
extern "C" void kernel_launch(void* const* d_in, const int* in_sizes, int n_in,
                              void* d_out, int out_size)
{
    const float* X   = (const float*)d_in[0];
    const int*   tid = (const int*)  d_in[1];
    const float* W0  = (const float*)d_in[2];
    const float* b0  = (const float*)d_in[3];
    const float* W1  = (const float*)d_in[4];
    const float* b1  = (const float*)d_in[5];
    float* out = (float*)d_out;

    cudaFuncSetAttribute(mot_routed_gemm,
                         cudaFuncAttributeMaxDynamicSharedMemorySize, SMEM_TOTAL);

    zero_cnt<<<1, 32>>>();
    compact_tokens<<<TOK / 256, 256>>>(tid);
    halve_x<<<(TOK * DIM / 4) / 256, 256>>>((const float4*)X);
    transpose_w<<<dim3(OUTD / 32, DIM / 32, 2), dim3(32, 8)>>>(W0, W1);

    dim3 grid(OUTD / BN, 128);               // 32 x (2 experts * 64 row tiles)
    mot_routed_gemm<<<grid, NTHREADS, SMEM_TOTAL>>>(b0, b1, out);
}